// round 16
// baseline (speedup 1.0000x reference)
#include <cuda_runtime.h>
#include <cuda_bf16.h>
#include <cstdint>

// Inputs (metadata order):
//   0: x          float32 [200000]
//   1: Param_W    float32 [1000000]
//   2: Param_b    float32 [500]
//   3: src        int32   [12800000]
//   4: dst        int32   [12800000]
//   5: weight_idx int32   [12800000]
//   6: node_label int32   [200000]
// Output: y float32 [200000]
//
// Converged structure (record: 140.0 us):
//   memset(y, 0)  ->  ONE fused kernel:
//     - every thread: 4 edges (3 streaming LDG.128 + 8 random gathers +
//       4 RED.E.ADD) — the calibrated floor shape (~3 random L1tex
//       wavefronts per edge, L1=L2~88%)
//     - the LAST 50K threads additionally add the label-indexed bias for
//       4 nodes each; they execute in the final partial wave (~55% full),
//       so the extra atomics ride on otherwise-idle resources.
//   All contributions are atomic adds into a zeroed buffer -> order-free.

__global__ void __launch_bounds__(256, 8)
edge_scatter_fused_kernel(const float* __restrict__ x,
                          const float* __restrict__ Param_W,
                          const float* __restrict__ Param_b,
                          const int4* __restrict__ src4,
                          const int4* __restrict__ dst4,
                          const int4* __restrict__ wi4,
                          const int4* __restrict__ node_label4,
                          float* __restrict__ y,
                          int n_vec,
                          int bias_offset,   // = n_vec - n_node_vec (>=0)
                          int n_node_vec) {
    int i = blockIdx.x * blockDim.x + threadIdx.x;

    if (i < n_vec) {
        int4 s = src4[i];
        int4 w = wi4[i];
        int4 d = dst4[i];

        float m0 = __ldg(&Param_W[w.x]) * __ldg(&x[s.x]);
        float m1 = __ldg(&Param_W[w.y]) * __ldg(&x[s.y]);
        float m2 = __ldg(&Param_W[w.z]) * __ldg(&x[s.z]);
        float m3 = __ldg(&Param_W[w.w]) * __ldg(&x[s.w]);

        atomicAdd(&y[d.x], m0);
        atomicAdd(&y[d.y], m1);
        atomicAdd(&y[d.z], m2);
        atomicAdd(&y[d.w], m3);
    }

    // Tail-wave bias add: single unsigned range check (one ISETP).
    unsigned j = (unsigned)(i - bias_offset);
    if (j < (unsigned)n_node_vec) {
        int4 l = node_label4[j];
        int base = (int)j * 4;
        atomicAdd(&y[base + 0], __ldg(&Param_b[l.x]));
        atomicAdd(&y[base + 1], __ldg(&Param_b[l.y]));
        atomicAdd(&y[base + 2], __ldg(&Param_b[l.z]));
        atomicAdd(&y[base + 3], __ldg(&Param_b[l.w]));
    }
}

// Scalar tails (not hit for these sizes: 12.8M % 4 == 0, 200K % 4 == 0).
__global__ void edge_scatter_tail_kernel(const float* __restrict__ x,
                                         const float* __restrict__ Param_W,
                                         const int* __restrict__ src,
                                         const int* __restrict__ dst,
                                         const int* __restrict__ wi,
                                         float* __restrict__ y,
                                         int start, int n_edges) {
    int i = start + blockIdx.x * blockDim.x + threadIdx.x;
    if (i < n_edges) {
        float m = __ldg(&Param_W[wi[i]]) * __ldg(&x[src[i]]);
        atomicAdd(&y[dst[i]], m);
    }
}

__global__ void bias_tail_kernel(const float* __restrict__ Param_b,
                                 const int* __restrict__ node_label,
                                 float* __restrict__ y,
                                 int start, int n_nodes) {
    int i = start + blockIdx.x * blockDim.x + threadIdx.x;
    if (i < n_nodes) {
        atomicAdd(&y[i], __ldg(&Param_b[node_label[i]]));
    }
}

extern "C" void kernel_launch(void* const* d_in, const int* in_sizes, int n_in,
                              void* d_out, int out_size) {
    const float* x          = (const float*)d_in[0];
    const float* Param_W    = (const float*)d_in[1];
    const float* Param_b    = (const float*)d_in[2];
    const int*   src        = (const int*)d_in[3];
    const int*   dst        = (const int*)d_in[4];
    const int*   weight_idx = (const int*)d_in[5];
    const int*   node_label = (const int*)d_in[6];
    float* y = (float*)d_out;

    int n_nodes = in_sizes[0];
    int n_edges = in_sizes[3];

    // 1) y = 0 (memset node; the fused kernel's only dependency)
    cudaMemsetAsync(y, 0, (size_t)out_size * sizeof(float));

    // 2) fused scatter-add (edges) + tail-wave bias add (nodes), one kernel.
    int n_vec = n_edges / 4;
    int n_node_vec = n_nodes / 4;
    int bias_offset = n_vec - n_node_vec;
    if (bias_offset < 0) bias_offset = 0;
    {
        const int threads = 256;
        long long total_work = (long long)bias_offset + n_node_vec;
        if (total_work < n_vec) total_work = n_vec;
        long long want = (total_work + threads - 1) / threads;
        long long cap = 2147483647LL;
        int blocks = (int)(want > cap ? cap : want);
        if (blocks < 1) blocks = 1;
        edge_scatter_fused_kernel<<<blocks, threads>>>(
            x, Param_W, Param_b,
            (const int4*)src, (const int4*)dst, (const int4*)weight_idx,
            (const int4*)node_label,
            y, n_vec, bias_offset, n_node_vec);
    }

    // 3) tails (no-ops for these sizes)
    int e_start = n_vec * 4;
    int e_rem = n_edges - e_start;
    if (e_rem > 0) {
        int threads = 256;
        int blocks = (e_rem + threads - 1) / threads;
        edge_scatter_tail_kernel<<<blocks, threads>>>(
            x, Param_W, src, dst, weight_idx, y, e_start, n_edges);
    }
    int b_start = n_node_vec * 4;
    int b_rem = n_nodes - b_start;
    if (b_rem > 0) {
        int threads = 256;
        int blocks = (b_rem + threads - 1) / threads;
        bias_tail_kernel<<<blocks, threads>>>(
            Param_b, node_label, y, b_start, n_nodes);
    }
}